// round 1
// baseline (speedup 1.0000x reference)
#include <cuda_runtime.h>
#include <cstddef>

// ---------------------------------------------------------------------------
// Static scratch (no allocation allowed in kernel_launch)
// ---------------------------------------------------------------------------
#define NMAX 50000

__device__ float g_agg1[NMAX * 2];
__device__ float g_h1[(size_t)NMAX * 128];
__device__ float g_y[(size_t)NMAX * 64];
__device__ float g_r[(size_t)NMAX * 64];
__device__ float g_agg[(size_t)NMAX * 64];
__device__ float g_h2[(size_t)NMAX * 64];
__device__ float g_u[(size_t)NMAX * 128];
__device__ float g_v[(size_t)NMAX * 128];

// ---------------------------------------------------------------------------
// Layer 1 scatter: agg1[dst] += x[src] * ew   (2 features, vector red)
// ---------------------------------------------------------------------------
__global__ void scatter_f2(const int* __restrict__ src, const int* __restrict__ dst,
                           const float* __restrict__ ew, const float* __restrict__ x,
                           float* __restrict__ agg, int E) {
    int e = blockIdx.x * blockDim.x + threadIdx.x;
    if (e >= E) return;
    int s = src[e];
    int d = dst[e];
    float w = ew[e];
    float2 xv = __ldg((const float2*)(x + 2 * (size_t)s));
    asm volatile("red.global.add.v2.f32 [%0], {%1, %2};"
                 :: "l"(agg + 2 * (size_t)d), "f"(xv.x * w), "f"(xv.y * w)
                 : "memory");
}

// ---------------------------------------------------------------------------
// Layer 1 combine: h1 = relu(agg1 @ W1_rel + x @ W1_root + b1)   (2 -> 128)
// ---------------------------------------------------------------------------
__global__ void layer1_kernel(const float* __restrict__ x,
                              const float* __restrict__ agg1,
                              const float* __restrict__ W1_rel,
                              const float* __restrict__ W1_root,
                              const float* __restrict__ b1,
                              float* __restrict__ h1, int N) {
    int tid = blockIdx.x * blockDim.x + threadIdx.x;
    if (tid >= N * 128) return;
    int n = tid >> 7;
    int f = tid & 127;
    float a0 = agg1[2 * n], a1 = agg1[2 * n + 1];
    float x0 = x[2 * n], x1 = x[2 * n + 1];
    float v = a0 * W1_rel[f] + a1 * W1_rel[128 + f]
            + x0 * W1_root[f] + x1 * W1_root[128 + f] + b1[f];
    h1[tid] = fmaxf(v, 0.f);
}

// ---------------------------------------------------------------------------
// Dual GEMM: Oa = H @ Wa (+ba), Ob = H @ Wb (+bb).  H is [N, IN] row-major,
// W are [IN, OUT] row-major. Block = 2*OUT threads, node-tile NT=16 kept
// transposed in smem so the k-inner loop does float4 broadcasts.
// ---------------------------------------------------------------------------
template <int IN, int OUT>
__global__ void gemm_dual(const float* __restrict__ H,
                          const float* __restrict__ Wa,
                          const float* __restrict__ Wb,
                          const float* __restrict__ ba,
                          const float* __restrict__ bb,
                          float* __restrict__ Oa,
                          float* __restrict__ Ob, int N) {
    constexpr int NT = 16;
    constexpr int SJ = 20;  // padded row stride (floats), 16B-aligned rows
    __shared__ float sh[IN * SJ];

    int n0 = blockIdx.x * NT;
    int t = threadIdx.x;  // 0 .. 2*OUT-1

    // Fill smem transposed: sh[k*SJ + j] = H[(n0+j)*IN + k]
    for (int idx = t; idx < NT * IN; idx += blockDim.x) {
        int j = idx / IN;
        int k = idx - j * IN;
        int n = n0 + j;
        sh[k * SJ + j] = (n < N) ? H[(size_t)n * IN + k] : 0.f;
    }
    __syncthreads();

    const float* W = (t < OUT) ? Wa : Wb;
    int col = (t < OUT) ? t : (t - OUT);

    float acc[NT];
#pragma unroll
    for (int j = 0; j < NT; j++) acc[j] = 0.f;

#pragma unroll 4
    for (int k = 0; k < IN; k++) {
        float w = __ldg(W + k * OUT + col);
        const float4* s4 = (const float4*)(sh + k * SJ);
#pragma unroll
        for (int jg = 0; jg < NT / 4; jg++) {
            float4 h4 = s4[jg];
            acc[4 * jg + 0] += h4.x * w;
            acc[4 * jg + 1] += h4.y * w;
            acc[4 * jg + 2] += h4.z * w;
            acc[4 * jg + 3] += h4.w * w;
        }
    }

    const float* bp = (t < OUT) ? ba : bb;
    float b = bp ? bp[col] : 0.f;
    float* O = (t < OUT) ? Oa : Ob;
#pragma unroll
    for (int j = 0; j < NT; j++) {
        int n = n0 + j;
        if (n < N) O[(size_t)n * OUT + col] = acc[j] + b;
    }
}

// ---------------------------------------------------------------------------
// 64-feature scatter: agg[dst] += y[src] * ew, 16 threads/edge, red.v4
// ---------------------------------------------------------------------------
__global__ void scatter64(const int* __restrict__ src, const int* __restrict__ dst,
                          const float* __restrict__ ew, const float* __restrict__ y,
                          float* __restrict__ agg, int E) {
    int tid = blockIdx.x * blockDim.x + threadIdx.x;
    int e = tid >> 4;
    if (e >= E) return;
    int c = tid & 15;
    int s = src[e];
    int d = dst[e];
    float w = ew[e];
    float4 yv = __ldg((const float4*)(y + (size_t)s * 64 + c * 4));
    asm volatile("red.global.add.v4.f32 [%0], {%1, %2, %3, %4};"
                 :: "l"(agg + (size_t)d * 64 + c * 4),
                    "f"(yv.x * w), "f"(yv.y * w), "f"(yv.z * w), "f"(yv.w * w)
                 : "memory");
}

// ---------------------------------------------------------------------------
// Elementwise: o = (a + r), optional relu
// ---------------------------------------------------------------------------
__global__ void add_act(const float* __restrict__ a, const float* __restrict__ r,
                        float* __restrict__ o, int n, int do_relu) {
    int i = blockIdx.x * blockDim.x + threadIdx.x;
    if (i >= n) return;
    float v = a[i] + r[i];
    o[i] = do_relu ? fmaxf(v, 0.f) : v;
}

// ---------------------------------------------------------------------------
// Decoder: pred[e] = relu(u[s[e]] + v[d[e]]) . dec_W2 + dec_b2 ; duplicate.
// One warp per observed edge, lane = one float4 (32*4 = 128 feats).
// ---------------------------------------------------------------------------
__global__ void decode_edges(const int* __restrict__ src, const int* __restrict__ dst,
                             const float* __restrict__ u, const float* __restrict__ v,
                             const float* __restrict__ W2, const float* __restrict__ b2,
                             float* __restrict__ pred, int OBS) {
    int gt = blockIdx.x * blockDim.x + threadIdx.x;
    int warp = gt >> 5;
    int lane = gt & 31;
    if (warp >= OBS) return;
    int s = src[warp];
    int d = dst[warp];
    float4 uu = __ldg((const float4*)(u + (size_t)s * 128) + lane);
    float4 vv = __ldg((const float4*)(v + (size_t)d * 128) + lane);
    float4 ww = __ldg((const float4*)(W2) + lane);
    float acc = fmaxf(uu.x + vv.x, 0.f) * ww.x
              + fmaxf(uu.y + vv.y, 0.f) * ww.y
              + fmaxf(uu.z + vv.z, 0.f) * ww.z
              + fmaxf(uu.w + vv.w, 0.f) * ww.w;
#pragma unroll
    for (int o = 16; o > 0; o >>= 1) acc += __shfl_xor_sync(0xFFFFFFFFu, acc, o);
    if (lane == 0) {
        float p = acc + __ldg(b2);
        pred[warp] = p;
        pred[warp + OBS] = p;
    }
}

// ---------------------------------------------------------------------------
// Launch
// ---------------------------------------------------------------------------
extern "C" void kernel_launch(void* const* d_in, const int* in_sizes, int n_in,
                              void* d_out, int out_size) {
    const float* x       = (const float*)d_in[0];
    const int*   ei      = (const int*)d_in[1];
    const float* ew      = (const float*)d_in[2];
    // d_in[3] = num_obs (scalar on device); E = 2*num_obs by construction
    const float* W1_rel  = (const float*)d_in[4];
    const float* b1      = (const float*)d_in[5];
    const float* W1_root = (const float*)d_in[6];
    const float* W2_rel  = (const float*)d_in[7];
    const float* b2      = (const float*)d_in[8];
    const float* W2_root = (const float*)d_in[9];
    const float* W3_rel  = (const float*)d_in[10];
    const float* b3      = (const float*)d_in[11];
    const float* W3_root = (const float*)d_in[12];
    const float* dW1     = (const float*)d_in[13];
    const float* db1     = (const float*)d_in[14];
    const float* dW2     = (const float*)d_in[15];
    const float* db2     = (const float*)d_in[16];

    int N   = in_sizes[0] / 2;
    int E   = in_sizes[2];
    int OBS = E / 2;

    const int* src = ei;
    const int* dst = ei + E;

    float* out = (float*)d_out;
    float* z   = out + 2 * (size_t)OBS;  // output layout: [pred_full | z]

    float *agg1, *h1, *y, *r, *agg, *h2, *u, *v;
    cudaGetSymbolAddress((void**)&agg1, g_agg1);
    cudaGetSymbolAddress((void**)&h1,   g_h1);
    cudaGetSymbolAddress((void**)&y,    g_y);
    cudaGetSymbolAddress((void**)&r,    g_r);
    cudaGetSymbolAddress((void**)&agg,  g_agg);
    cudaGetSymbolAddress((void**)&h2,   g_h2);
    cudaGetSymbolAddress((void**)&u,    g_u);
    cudaGetSymbolAddress((void**)&v,    g_v);

    const int TB = 256;

    // ---- Layer 1: agg first (2 feats), then tiny matmul ----
    cudaMemsetAsync(agg1, 0, (size_t)N * 2 * sizeof(float));
    scatter_f2<<<(E + TB - 1) / TB, TB>>>(src, dst, ew, x, agg1, E);
    layer1_kernel<<<(N * 128 + TB - 1) / TB, TB>>>(x, agg1, W1_rel, W1_root, b1, h1, N);

    // ---- Layer 2: matmul first (128->64), scatter 64 feats ----
    gemm_dual<128, 64><<<(N + 15) / 16, 128>>>(h1, W2_rel, W2_root, nullptr, b2, y, r, N);
    cudaMemsetAsync(agg, 0, (size_t)N * 64 * sizeof(float));
    scatter64<<<(E * 16 + TB - 1) / TB, TB>>>(src, dst, ew, y, agg, E);
    add_act<<<(N * 64 + TB - 1) / TB, TB>>>(agg, r, h2, N * 64, 1);

    // ---- Layer 3: same (64->64), no relu; z goes straight into d_out ----
    gemm_dual<64, 64><<<(N + 15) / 16, 128>>>(h2, W3_rel, W3_root, nullptr, b3, y, r, N);
    cudaMemsetAsync(agg, 0, (size_t)N * 64 * sizeof(float));
    scatter64<<<(E * 16 + TB - 1) / TB, TB>>>(src, dst, ew, y, agg, E);
    add_act<<<(N * 64 + TB - 1) / TB, TB>>>(agg, r, z, N * 64, 0);

    // ---- Decoder: node-level u = z@A + b, v = z@B, then warp-per-edge ----
    gemm_dual<64, 128><<<(N + 15) / 16, 256>>>(z, dW1, dW1 + 64 * 128, db1, nullptr, u, v, N);
    decode_edges<<<(OBS * 32 + TB - 1) / TB, TB>>>(src, dst, u, v, dW2, db2, out, OBS);
}

// round 2
// speedup vs baseline: 1.2861x; 1.2861x over previous
#include <cuda_runtime.h>
#include <cuda_fp16.h>
#include <cstddef>

// ---------------------------------------------------------------------------
// Static scratch (no allocation allowed in kernel_launch)
// ---------------------------------------------------------------------------
#define NMAX 50000
#define EMAX 1600000

__device__ float g_agg1[NMAX * 2];
__device__ float g_h1[(size_t)NMAX * 128];
__device__ float g_y[(size_t)NMAX * 64];
__device__ float g_r[(size_t)NMAX * 64];
__device__ float g_h2[(size_t)NMAX * 64];
__device__ __half g_u[(size_t)NMAX * 128];
__device__ __half g_v[(size_t)NMAX * 128];

// CSR scratch
__device__ int  g_cnt[NMAX];
__device__ int  g_roff[NMAX + 1];
__device__ int  g_cursor[NMAX];
__device__ int2 g_csr[EMAX];

// ---------------------------------------------------------------------------
// CSR build: histogram by dst
// ---------------------------------------------------------------------------
__global__ void hist_kernel(const int* __restrict__ dst, int* __restrict__ cnt, int E) {
    int e = blockIdx.x * blockDim.x + threadIdx.x;
    if (e >= E) return;
    atomicAdd(&cnt[dst[e]], 1);
}

// Single-block exclusive scan (warp-shuffle based), writes roff[N+1] and cursor copy.
__global__ void scan_counts(const int* __restrict__ cnt, int* __restrict__ roff,
                            int* __restrict__ cursor, int N) {
    __shared__ int wsum[32];
    __shared__ int carry;
    int tid = threadIdx.x;
    int lane = tid & 31, wid = tid >> 5;
    if (tid == 0) carry = 0;
    __syncthreads();
    int nchunk = (N + 1023) >> 10;
    for (int c = 0; c < nchunk; c++) {
        int i = (c << 10) + tid;
        int v = (i < N) ? cnt[i] : 0;
        // inclusive warp scan
        int s = v;
#pragma unroll
        for (int o = 1; o < 32; o <<= 1) {
            int t = __shfl_up_sync(0xFFFFFFFFu, s, o);
            if (lane >= o) s += t;
        }
        if (lane == 31) wsum[wid] = s;
        __syncthreads();
        if (wid == 0) {
            int ws = wsum[lane];
#pragma unroll
            for (int o = 1; o < 32; o <<= 1) {
                int t = __shfl_up_sync(0xFFFFFFFFu, ws, o);
                if (lane >= o) ws += t;
            }
            wsum[lane] = ws;  // inclusive scan of warp sums
        }
        __syncthreads();
        int base = carry + (wid > 0 ? wsum[wid - 1] : 0);
        int excl = base + s - v;
        if (i < N) { roff[i] = excl; cursor[i] = excl; }
        __syncthreads();  // everyone done reading carry/wsum
        if (tid == 1023) carry += wsum[31];
        __syncthreads();
    }
    if (tid == 0) roff[N] = carry;
}

// Fill CSR buckets: csr[p] = (src, bits(ew)), grouped by dst
__global__ void fill_kernel(const int* __restrict__ src, const int* __restrict__ dst,
                            const float* __restrict__ ew, int* __restrict__ cursor,
                            int2* __restrict__ csr, int E) {
    int e = blockIdx.x * blockDim.x + threadIdx.x;
    if (e >= E) return;
    int d = dst[e];
    int p = atomicAdd(&cursor[d], 1);
    csr[p] = make_int2(src[e], __float_as_int(ew[e]));
}

// ---------------------------------------------------------------------------
// Layer 1 gather: agg1[n] = sum_{e: dst=n} x[src[e]] * w   (2 feats, 1 thr/node)
// ---------------------------------------------------------------------------
__global__ void gather_l1(const int2* __restrict__ csr, const int* __restrict__ roff,
                          const float* __restrict__ x, float* __restrict__ agg1, int N) {
    int n = blockIdx.x * blockDim.x + threadIdx.x;
    if (n >= N) return;
    int beg = __ldg(roff + n), end = __ldg(roff + n + 1);
    float a0 = 0.f, a1 = 0.f;
    for (int i = beg; i < end; i++) {
        int2 p = __ldg(csr + i);
        float w = __int_as_float(p.y);
        float2 xv = __ldg((const float2*)(x + 2 * (size_t)p.x));
        a0 += w * xv.x;
        a1 += w * xv.y;
    }
    ((float2*)agg1)[n] = make_float2(a0, a1);
}

// ---------------------------------------------------------------------------
// Layer 1 combine: h1 = relu(agg1 @ W1_rel + x @ W1_root + b1)   (2 -> 128)
// ---------------------------------------------------------------------------
__global__ void layer1_kernel(const float* __restrict__ x,
                              const float* __restrict__ agg1,
                              const float* __restrict__ W1_rel,
                              const float* __restrict__ W1_root,
                              const float* __restrict__ b1,
                              float* __restrict__ h1, int N) {
    int tid = blockIdx.x * blockDim.x + threadIdx.x;
    if (tid >= N * 128) return;
    int n = tid >> 7;
    int f = tid & 127;
    float a0 = agg1[2 * n], a1 = agg1[2 * n + 1];
    float x0 = x[2 * n], x1 = x[2 * n + 1];
    float v = a0 * W1_rel[f] + a1 * W1_rel[128 + f]
            + x0 * W1_root[f] + x1 * W1_root[128 + f] + b1[f];
    h1[tid] = fmaxf(v, 0.f);
}

// ---------------------------------------------------------------------------
// Dual GEMM: Oa = H @ Wa (+ba), Ob = H @ Wb (+bb).  Optional half output.
// ---------------------------------------------------------------------------
template <int IN, int OUT, typename TOut>
__global__ void gemm_dual(const float* __restrict__ H,
                          const float* __restrict__ Wa,
                          const float* __restrict__ Wb,
                          const float* __restrict__ ba,
                          const float* __restrict__ bb,
                          TOut* __restrict__ Oa,
                          TOut* __restrict__ Ob, int N) {
    constexpr int NT = 16;
    constexpr int SJ = 20;
    __shared__ float sh[IN * SJ];

    int n0 = blockIdx.x * NT;
    int t = threadIdx.x;

    for (int idx = t; idx < NT * IN; idx += blockDim.x) {
        int j = idx / IN;
        int k = idx - j * IN;
        int n = n0 + j;
        sh[k * SJ + j] = (n < N) ? H[(size_t)n * IN + k] : 0.f;
    }
    __syncthreads();

    const float* W = (t < OUT) ? Wa : Wb;
    int col = (t < OUT) ? t : (t - OUT);

    float acc[NT];
#pragma unroll
    for (int j = 0; j < NT; j++) acc[j] = 0.f;

#pragma unroll 4
    for (int k = 0; k < IN; k++) {
        float w = __ldg(W + k * OUT + col);
        const float4* s4 = (const float4*)(sh + k * SJ);
#pragma unroll
        for (int jg = 0; jg < NT / 4; jg++) {
            float4 h4 = s4[jg];
            acc[4 * jg + 0] += h4.x * w;
            acc[4 * jg + 1] += h4.y * w;
            acc[4 * jg + 2] += h4.z * w;
            acc[4 * jg + 3] += h4.w * w;
        }
    }

    const float* bp = (t < OUT) ? ba : bb;
    float b = bp ? bp[col] : 0.f;
    TOut* O = (t < OUT) ? Oa : Ob;
#pragma unroll
    for (int j = 0; j < NT; j++) {
        int n = n0 + j;
        if (n < N) O[(size_t)n * OUT + col] = (TOut)(acc[j] + b);
    }
}

// ---------------------------------------------------------------------------
// Fused gather + residual + act:  out[n] = act( sum w*y[src] + r[n] )
// 8 lanes/node, each lane owns 8 feats (two float4s). No atomics.
// ---------------------------------------------------------------------------
__global__ void gather64(const int2* __restrict__ csr, const int* __restrict__ roff,
                         const float* __restrict__ y, const float* __restrict__ r,
                         float* __restrict__ out, int N, int do_relu) {
    int node = blockIdx.x * 32 + (threadIdx.x >> 3);
    int c = threadIdx.x & 7;
    if (node >= N) return;
    int beg = __ldg(roff + node);
    int end = __ldg(roff + node + 1);
    float4 a0 = make_float4(0, 0, 0, 0);
    float4 a1 = make_float4(0, 0, 0, 0);
    int i = beg;
    for (; i + 2 <= end; i += 2) {
        int2 p0 = __ldg(csr + i);
        int2 p1 = __ldg(csr + i + 1);
        const float4* r0 = (const float4*)(y + (size_t)p0.x * 64);
        const float4* r1 = (const float4*)(y + (size_t)p1.x * 64);
        float4 u0 = __ldg(r0 + c);
        float4 u1 = __ldg(r0 + c + 8);
        float4 v0 = __ldg(r1 + c);
        float4 v1 = __ldg(r1 + c + 8);
        float w0 = __int_as_float(p0.y);
        float w1 = __int_as_float(p1.y);
        a0.x += w0 * u0.x; a0.y += w0 * u0.y; a0.z += w0 * u0.z; a0.w += w0 * u0.w;
        a1.x += w0 * u1.x; a1.y += w0 * u1.y; a1.z += w0 * u1.z; a1.w += w0 * u1.w;
        a0.x += w1 * v0.x; a0.y += w1 * v0.y; a0.z += w1 * v0.z; a0.w += w1 * v0.w;
        a1.x += w1 * v1.x; a1.y += w1 * v1.y; a1.z += w1 * v1.z; a1.w += w1 * v1.w;
    }
    if (i < end) {
        int2 p0 = __ldg(csr + i);
        const float4* r0 = (const float4*)(y + (size_t)p0.x * 64);
        float4 u0 = __ldg(r0 + c);
        float4 u1 = __ldg(r0 + c + 8);
        float w0 = __int_as_float(p0.y);
        a0.x += w0 * u0.x; a0.y += w0 * u0.y; a0.z += w0 * u0.z; a0.w += w0 * u0.w;
        a1.x += w0 * u1.x; a1.y += w0 * u1.y; a1.z += w0 * u1.z; a1.w += w0 * u1.w;
    }
    const float4* rp = (const float4*)(r + (size_t)node * 64);
    float4 rv0 = __ldg(rp + c);
    float4 rv1 = __ldg(rp + c + 8);
    a0.x += rv0.x; a0.y += rv0.y; a0.z += rv0.z; a0.w += rv0.w;
    a1.x += rv1.x; a1.y += rv1.y; a1.z += rv1.z; a1.w += rv1.w;
    if (do_relu) {
        a0.x = fmaxf(a0.x, 0.f); a0.y = fmaxf(a0.y, 0.f);
        a0.z = fmaxf(a0.z, 0.f); a0.w = fmaxf(a0.w, 0.f);
        a1.x = fmaxf(a1.x, 0.f); a1.y = fmaxf(a1.y, 0.f);
        a1.z = fmaxf(a1.z, 0.f); a1.w = fmaxf(a1.w, 0.f);
    }
    float4* op = (float4*)(out + (size_t)node * 64);
    op[c] = a0;
    op[c + 8] = a1;
}

// ---------------------------------------------------------------------------
// Decoder: pred[e] = relu(u[s]+v[d]) . dec_W2 + dec_b2 ; duplicated.
// u, v in fp16. 16 threads/edge, lane owns 8 feats.
// ---------------------------------------------------------------------------
__global__ void decode_edges_h(const int* __restrict__ src, const int* __restrict__ dst,
                               const __half* __restrict__ u, const __half* __restrict__ v,
                               const float* __restrict__ W2, const float* __restrict__ b2,
                               float* __restrict__ pred, int OBS) {
    int gt = blockIdx.x * blockDim.x + threadIdx.x;
    int e = gt >> 4;
    int c = gt & 15;
    if (e >= OBS) return;
    int s = src[e];
    int d = dst[e];
    uint4 ub = __ldg((const uint4*)(u + (size_t)s * 128) + c);
    uint4 vb = __ldg((const uint4*)(v + (size_t)d * 128) + c);
    float4 w0 = __ldg((const float4*)W2 + 2 * c);
    float4 w1 = __ldg((const float4*)W2 + 2 * c + 1);
    const half2 z2 = __float2half2_rn(0.f);

    half2 h0 = __hmax2(__hadd2(*(const half2*)&ub.x, *(const half2*)&vb.x), z2);
    half2 h1 = __hmax2(__hadd2(*(const half2*)&ub.y, *(const half2*)&vb.y), z2);
    half2 h2 = __hmax2(__hadd2(*(const half2*)&ub.z, *(const half2*)&vb.z), z2);
    half2 h3 = __hmax2(__hadd2(*(const half2*)&ub.w, *(const half2*)&vb.w), z2);

    float2 f0 = __half22float2(h0);
    float2 f1 = __half22float2(h1);
    float2 f2 = __half22float2(h2);
    float2 f3 = __half22float2(h3);

    float acc = f0.x * w0.x + f0.y * w0.y + f1.x * w0.z + f1.y * w0.w
              + f2.x * w1.x + f2.y * w1.y + f3.x * w1.z + f3.y * w1.w;
#pragma unroll
    for (int o = 8; o > 0; o >>= 1) acc += __shfl_xor_sync(0xFFFFFFFFu, acc, o);
    if (c == 0) {
        float p = acc + __ldg(b2);
        pred[e] = p;
        pred[e + OBS] = p;
    }
}

// ---------------------------------------------------------------------------
// Launch
// ---------------------------------------------------------------------------
extern "C" void kernel_launch(void* const* d_in, const int* in_sizes, int n_in,
                              void* d_out, int out_size) {
    const float* x       = (const float*)d_in[0];
    const int*   ei      = (const int*)d_in[1];
    const float* ew      = (const float*)d_in[2];
    const float* W1_rel  = (const float*)d_in[4];
    const float* b1      = (const float*)d_in[5];
    const float* W1_root = (const float*)d_in[6];
    const float* W2_rel  = (const float*)d_in[7];
    const float* b2      = (const float*)d_in[8];
    const float* W2_root = (const float*)d_in[9];
    const float* W3_rel  = (const float*)d_in[10];
    const float* b3      = (const float*)d_in[11];
    const float* W3_root = (const float*)d_in[12];
    const float* dW1     = (const float*)d_in[13];
    const float* db1     = (const float*)d_in[14];
    const float* dW2     = (const float*)d_in[15];
    const float* db2     = (const float*)d_in[16];

    int N   = in_sizes[0] / 2;
    int E   = in_sizes[2];
    int OBS = E / 2;

    const int* src = ei;
    const int* dst = ei + E;

    float* out = (float*)d_out;
    float* z   = out + 2 * (size_t)OBS;  // output layout: [pred_full | z]

    float *agg1, *h1, *y, *r, *h2;
    __half *u, *v;
    int *cnt, *roff, *cursor;
    int2* csr;
    cudaGetSymbolAddress((void**)&agg1,   g_agg1);
    cudaGetSymbolAddress((void**)&h1,     g_h1);
    cudaGetSymbolAddress((void**)&y,      g_y);
    cudaGetSymbolAddress((void**)&r,      g_r);
    cudaGetSymbolAddress((void**)&h2,     g_h2);
    cudaGetSymbolAddress((void**)&u,      g_u);
    cudaGetSymbolAddress((void**)&v,      g_v);
    cudaGetSymbolAddress((void**)&cnt,    g_cnt);
    cudaGetSymbolAddress((void**)&roff,   g_roff);
    cudaGetSymbolAddress((void**)&cursor, g_cursor);
    cudaGetSymbolAddress((void**)&csr,    g_csr);

    const int TB = 256;
    int eb = (E + TB - 1) / TB;

    // ---- Build dst-sorted CSR (used by all 3 aggregation layers) ----
    cudaMemsetAsync(cnt, 0, (size_t)N * sizeof(int));
    hist_kernel<<<eb, TB>>>(dst, cnt, E);
    scan_counts<<<1, 1024>>>(cnt, roff, cursor, N);
    fill_kernel<<<eb, TB>>>(src, dst, ew, cursor, csr, E);

    // ---- Layer 1: gather (2 feats), then tiny expansion matmul ----
    gather_l1<<<(N + TB - 1) / TB, TB>>>(csr, roff, x, agg1, N);
    layer1_kernel<<<(N * 128 + TB - 1) / TB, TB>>>(x, agg1, W1_rel, W1_root, b1, h1, N);

    // ---- Layer 2: matmul first (128->64), then fused gather+residual+relu ----
    gemm_dual<128, 64, float><<<(N + 15) / 16, 128>>>(h1, W2_rel, W2_root, nullptr, b2, y, r, N);
    gather64<<<(N + 31) / 32, TB>>>(csr, roff, y, r, h2, N, 1);

    // ---- Layer 3: same (64->64), z straight into d_out ----
    gemm_dual<64, 64, float><<<(N + 15) / 16, 128>>>(h2, W3_rel, W3_root, nullptr, b3, y, r, N);
    gather64<<<(N + 31) / 32, TB>>>(csr, roff, y, r, z, N, 0);

    // ---- Decoder: u = z@A + b (fp16), v = z@B (fp16), warp-per-edge dot ----
    gemm_dual<64, 128, __half><<<(N + 15) / 16, 256>>>(z, dW1, dW1 + 64 * 128, db1, nullptr, u, v, N);
    decode_edges_h<<<((size_t)OBS * 16 + TB - 1) / TB, TB>>>(src, dst, u, v, dW2, db2, out, OBS);
}